// round 4
// baseline (speedup 1.0000x reference)
#include <cuda_runtime.h>
#include <cuda_bf16.h>
#include <math.h>

// ---------------------------------------------------------------------------
// GCN via CSR-gather (atomic-free aggregation):
//   deg count -> exclusive scan -> CSR fill (one atomic pass)
//   gather1 (agg + relu + @W2, fused node2) ; gather2 (agg + sigmoid + MLP head)
// factorization: out[d] = dinv[d] * ( sum_{s in N(d)} g[s] + g[d] ),
//   g[i] = dinv[i] * (h[i]),  dinv[i] = rsqrt(indeg(i)+1)
// ---------------------------------------------------------------------------

#define MAX_N 1000000
#define MAX_E 16000000
#define NTHREADS 256
#define SCAN_T 256
#define SCAN_I 8
#define SCAN_TILE (SCAN_T * SCAN_I)   // 2048

__device__ int    g_deg[MAX_N];
__device__ int    g_rowptr[MAX_N + 1];
__device__ int    g_cursor[MAX_N];
__device__ int    g_bsum[1024];
__device__ int    g_csr[MAX_E];
__device__ float  g_dinv[MAX_N];
__device__ float4 g_featA[MAX_N];
__device__ float4 g_featB[MAX_N];

// packed weights in constant memory
// W1:0(8) b1:8(4) W2:12(12) b2:24(3) W3:27(12) b3:39(4) W4:43(12) b4:55(3) W5:58(3) b5:61(1)
__constant__ float cW[64];

__device__ __forceinline__ void f4add(float4& a, const float4& b) {
    a.x += b.x; a.y += b.y; a.z += b.z; a.w += b.w;
}

// ---- degree count ----
__global__ void k_deg(const int* __restrict__ dst, int E) {
    int i = (blockIdx.x * blockDim.x + threadIdx.x) * 4;
    if (i + 3 < E) {
        int4 d = *(const int4*)(dst + i);
        atomicAdd(&g_deg[d.x], 1);
        atomicAdd(&g_deg[d.y], 1);
        atomicAdd(&g_deg[d.z], 1);
        atomicAdd(&g_deg[d.w], 1);
    } else {
        for (int j = i; j < E; j++) atomicAdd(&g_deg[dst[j]], 1);
    }
}

// ---- exclusive scan of deg -> rowptr (3 kernels) ----
__global__ void k_scan1(int N) {
    __shared__ int wsum[SCAN_T / 32];
    int t = threadIdx.x;
    int base = blockIdx.x * SCAN_TILE + t * SCAN_I;
    int v[SCAN_I];
#pragma unroll
    for (int k = 0; k < SCAN_I; k++) { int idx = base + k; v[k] = (idx < N) ? g_deg[idx] : 0; }
    int tot = 0;
#pragma unroll
    for (int k = 0; k < SCAN_I; k++) { int t0 = v[k]; v[k] = tot; tot += t0; }  // local exclusive
    int lane = t & 31, wid = t >> 5;
    int x = tot;
    for (int d = 1; d < 32; d <<= 1) { int y = __shfl_up_sync(0xffffffffu, x, d); if (lane >= d) x += y; }
    int wexcl = x - tot;                 // exclusive within warp
    if (lane == 31) wsum[wid] = x;       // warp inclusive total
    __syncthreads();
    if (wid == 0) {
        int s = (lane < SCAN_T / 32) ? wsum[lane] : 0;
        int xs = s;
        for (int d = 1; d < 32; d <<= 1) { int y = __shfl_up_sync(0xffffffffu, xs, d); if (lane >= d) xs += y; }
        if (lane < SCAN_T / 32) wsum[lane] = xs - s;   // exclusive warp offsets
    }
    __syncthreads();
    int off = wexcl + wsum[wid];
#pragma unroll
    for (int k = 0; k < SCAN_I; k++) { int idx = base + k; if (idx < N) g_rowptr[idx] = off + v[k]; }
    if (t == SCAN_T - 1) g_bsum[blockIdx.x] = off + tot;   // block total
}

__global__ void k_scan2(int nblk) {
    __shared__ int sh[1024];
    int t = threadIdx.x;
    int v = (t < nblk) ? g_bsum[t] : 0;
    sh[t] = v;
    __syncthreads();
    for (int d = 1; d < 1024; d <<= 1) {
        int y = (t >= d) ? sh[t - d] : 0;
        __syncthreads();
        sh[t] += y;
        __syncthreads();
    }
    if (t < nblk) g_bsum[t] = sh[t] - v;   // exclusive
}

__global__ void k_scan3(int N, int E) {
    int i = blockIdx.x * blockDim.x + threadIdx.x;
    if (i < N) {
        int r = g_rowptr[i] + g_bsum[i / SCAN_TILE];
        g_rowptr[i] = r;
        g_cursor[i] = r;
    }
    if (i == 0) g_rowptr[N] = E;
}

// ---- node pass 1: dinv, featA = dinv*(x@W1) ----
__global__ void k_node1(const float* __restrict__ x, int N) {
    int i = blockIdx.x * blockDim.x + threadIdx.x;
    if (i >= N) return;
    float dinv = rsqrtf((float)(g_deg[i] + 1));
    float2 xv = ((const float2*)x)[i];
    float4 h;
    h.x = dinv * (xv.x * cW[0] + xv.y * cW[4]);
    h.y = dinv * (xv.x * cW[1] + xv.y * cW[5]);
    h.z = dinv * (xv.x * cW[2] + xv.y * cW[6]);
    h.w = dinv * (xv.x * cW[3] + xv.y * cW[7]);
    g_dinv[i]  = dinv;
    g_featA[i] = h;
}

// ---- CSR fill: csr[cursor[dst]++] = src ----
__global__ void k_fill(const int* __restrict__ src, const int* __restrict__ dst, int E) {
    int i = (blockIdx.x * blockDim.x + threadIdx.x) * 4;
    if (i + 3 < E) {
        int4 s = *(const int4*)(src + i);
        int4 d = *(const int4*)(dst + i);
        g_csr[atomicAdd(&g_cursor[d.x], 1)] = s.x;
        g_csr[atomicAdd(&g_cursor[d.y], 1)] = s.y;
        g_csr[atomicAdd(&g_cursor[d.z], 1)] = s.z;
        g_csr[atomicAdd(&g_cursor[d.w], 1)] = s.w;
    } else {
        for (int j = i; j < E; j++) g_csr[atomicAdd(&g_cursor[dst[j]], 1)] = src[j];
    }
}

// ---- gather layer 1 (+ fused node2): featB = dinv*(relu(dinv*sum + b1)@W2) ----
__global__ void k_gather1(int N) {
    int i = blockIdx.x * blockDim.x + threadIdx.x;
    if (i >= N) return;
    int start = g_rowptr[i];
    int end   = g_rowptr[i + 1];
    float4 s0 = g_featA[i];                       // self loop
    float4 s1 = make_float4(0.f, 0.f, 0.f, 0.f);
    float4 s2 = make_float4(0.f, 0.f, 0.f, 0.f);
    float4 s3 = make_float4(0.f, 0.f, 0.f, 0.f);
    int j = start;
    for (; j + 4 <= end; j += 4) {
        int a = g_csr[j], b = g_csr[j + 1], c = g_csr[j + 2], d = g_csr[j + 3];
        float4 fa = g_featA[a], fb = g_featA[b], fc = g_featA[c], fd = g_featA[d];
        f4add(s0, fa); f4add(s1, fb); f4add(s2, fc); f4add(s3, fd);
    }
    for (; j < end; j++) { float4 fa = g_featA[g_csr[j]]; f4add(s0, fa); }
    f4add(s0, s1); f4add(s2, s3); f4add(s0, s2);
    float dinv = g_dinv[i];
    float h0 = fmaxf(s0.x * dinv + cW[8],  0.0f);
    float h1 = fmaxf(s0.y * dinv + cW[9],  0.0f);
    float h2 = fmaxf(s0.z * dinv + cW[10], 0.0f);
    float h3 = fmaxf(s0.w * dinv + cW[11], 0.0f);
    float4 g;
    g.x = dinv * (h0 * cW[12] + h1 * cW[15] + h2 * cW[18] + h3 * cW[21]);
    g.y = dinv * (h0 * cW[13] + h1 * cW[16] + h2 * cW[19] + h3 * cW[22]);
    g.z = dinv * (h0 * cW[14] + h1 * cW[17] + h2 * cW[20] + h3 * cW[23]);
    g.w = 0.0f;
    g_featB[i] = g;
}

// ---- gather layer 2 (+ fused node3): sigmoid + MLP head -> out ----
__global__ void k_gather2(float* __restrict__ out, int N) {
    int i = blockIdx.x * blockDim.x + threadIdx.x;
    if (i >= N) return;
    int start = g_rowptr[i];
    int end   = g_rowptr[i + 1];
    float4 s0 = g_featB[i];                       // self loop
    float4 s1 = make_float4(0.f, 0.f, 0.f, 0.f);
    float4 s2 = make_float4(0.f, 0.f, 0.f, 0.f);
    float4 s3 = make_float4(0.f, 0.f, 0.f, 0.f);
    int j = start;
    for (; j + 4 <= end; j += 4) {
        int a = g_csr[j], b = g_csr[j + 1], c = g_csr[j + 2], d = g_csr[j + 3];
        float4 fa = g_featB[a], fb = g_featB[b], fc = g_featB[c], fd = g_featB[d];
        f4add(s0, fa); f4add(s1, fb); f4add(s2, fc); f4add(s3, fd);
    }
    for (; j < end; j++) { float4 fa = g_featB[g_csr[j]]; f4add(s0, fa); }
    f4add(s0, s1); f4add(s2, s3); f4add(s0, s2);
    float dinv = g_dinv[i];
    // sigmoid(dinv*sum + b2)
    float q0 = 1.0f / (1.0f + expf(-(s0.x * dinv + cW[24])));
    float q1 = 1.0f / (1.0f + expf(-(s0.y * dinv + cW[25])));
    float q2 = 1.0f / (1.0f + expf(-(s0.z * dinv + cW[26])));
    // h3 = relu(q @ W3[3,4] + b3)
    float u0 = fmaxf(q0 * cW[27] + q1 * cW[31] + q2 * cW[35] + cW[39], 0.0f);
    float u1 = fmaxf(q0 * cW[28] + q1 * cW[32] + q2 * cW[36] + cW[40], 0.0f);
    float u2 = fmaxf(q0 * cW[29] + q1 * cW[33] + q2 * cW[37] + cW[41], 0.0f);
    float u3 = fmaxf(q0 * cW[30] + q1 * cW[34] + q2 * cW[38] + cW[42], 0.0f);
    // h4 = relu(u @ W4[4,3] + b4)
    float v0 = fmaxf(u0 * cW[43] + u1 * cW[46] + u2 * cW[49] + u3 * cW[52] + cW[55], 0.0f);
    float v1 = fmaxf(u0 * cW[44] + u1 * cW[47] + u2 * cW[50] + u3 * cW[53] + cW[56], 0.0f);
    float v2 = fmaxf(u0 * cW[45] + u1 * cW[48] + u2 * cW[51] + u3 * cW[54] + cW[57], 0.0f);
    out[i] = v0 * cW[58] + v1 * cW[59] + v2 * cW[60] + cW[61];
}

extern "C" void kernel_launch(void* const* d_in, const int* in_sizes, int n_in,
                              void* d_out, int out_size) {
    const float* x    = (const float*)d_in[0];
    const int*   eidx = (const int*)d_in[1];
    int N = in_sizes[0] / 2;
    int E = in_sizes[1] / 2;
    const int* src = eidx;
    const int* dst = eidx + E;
    float* out = (float*)d_out;

    // weights -> constant memory (D2D memcpy nodes, graph-capturable)
    cudaMemcpyToSymbolAsync(cW, d_in[2],  8 * sizeof(float),  0 * sizeof(float), cudaMemcpyDeviceToDevice, 0); // W1
    cudaMemcpyToSymbolAsync(cW, d_in[3],  4 * sizeof(float),  8 * sizeof(float), cudaMemcpyDeviceToDevice, 0); // b1
    cudaMemcpyToSymbolAsync(cW, d_in[4], 12 * sizeof(float), 12 * sizeof(float), cudaMemcpyDeviceToDevice, 0); // W2
    cudaMemcpyToSymbolAsync(cW, d_in[5],  3 * sizeof(float), 24 * sizeof(float), cudaMemcpyDeviceToDevice, 0); // b2
    cudaMemcpyToSymbolAsync(cW, d_in[6], 12 * sizeof(float), 27 * sizeof(float), cudaMemcpyDeviceToDevice, 0); // W3
    cudaMemcpyToSymbolAsync(cW, d_in[7],  4 * sizeof(float), 39 * sizeof(float), cudaMemcpyDeviceToDevice, 0); // b3
    cudaMemcpyToSymbolAsync(cW, d_in[8], 12 * sizeof(float), 43 * sizeof(float), cudaMemcpyDeviceToDevice, 0); // W4
    cudaMemcpyToSymbolAsync(cW, d_in[9],  3 * sizeof(float), 55 * sizeof(float), cudaMemcpyDeviceToDevice, 0); // b4
    cudaMemcpyToSymbolAsync(cW, d_in[10], 3 * sizeof(float), 58 * sizeof(float), cudaMemcpyDeviceToDevice, 0); // W5
    cudaMemcpyToSymbolAsync(cW, d_in[11], 1 * sizeof(float), 61 * sizeof(float), cudaMemcpyDeviceToDevice, 0); // b5

    // zero degree counters
    void* degPtr = nullptr;
    cudaGetSymbolAddress(&degPtr, g_deg);
    cudaMemsetAsync(degPtr, 0, N * sizeof(int), 0);

    int nodeBlocks = (N + NTHREADS - 1) / NTHREADS;
    int edgeBlocks = ((E + 3) / 4 + NTHREADS - 1) / NTHREADS;
    int scanBlocks = (N + SCAN_TILE - 1) / SCAN_TILE;   // 489 for N=1M

    k_deg    <<<edgeBlocks, NTHREADS>>>(dst, E);
    k_scan1  <<<scanBlocks, SCAN_T>>>(N);
    k_scan2  <<<1, 1024>>>(scanBlocks);
    k_scan3  <<<nodeBlocks, NTHREADS>>>(N, E);
    k_node1  <<<nodeBlocks, NTHREADS>>>(x, N);
    k_fill   <<<edgeBlocks, NTHREADS>>>(src, dst, E);
    k_gather1<<<nodeBlocks, NTHREADS>>>(N);
    k_gather2<<<nodeBlocks, NTHREADS>>>(out, N);
}

// round 6
// speedup vs baseline: 1.2893x; 1.2893x over previous
#include <cuda_runtime.h>
#include <cuda_bf16.h>
#include <math.h>

// ---------------------------------------------------------------------------
// GCN, RED-scatter formulation with rank-2 layer-1 aggregation:
//   deg -> node1 (y = dinv*x, float2) -> scatter1 (red.v2)
//       -> node2 (h1 = relu(dinv*(S@W1)+b1); featB = dinv*(h1@W2)) -> scatter2 (red.v4)
//       -> node3 (sigmoid + MLP head)
// gcnconv: out[d] = dinv[d] * ( sum_{s in N(d)} g[s] + g[d] ),  dinv = rsqrt(deg+1)
// ---------------------------------------------------------------------------

#define MAX_N 1000000
#define NTHREADS 256

__device__ int    g_deg[MAX_N];
__device__ float  g_dinv[MAX_N];
__device__ float2 g_y[MAX_N];      // layer-1 gather source (dinv * x), 8B
__device__ float2 g_accA[MAX_N];   // layer-1 accumulator
__device__ float4 g_featB[MAX_N];  // layer-2 gather source (dinv * h1@W2, w=0)
__device__ float4 g_accB[MAX_N];   // layer-2 accumulator

// packed weights in constant memory
// W1:0(8) b1:8(4) W2:12(12) b2:24(3) W3:27(12) b3:39(4) W4:43(12) b4:55(3) W5:58(3) b5:61(1)
__constant__ float cW[64];

__device__ __forceinline__ void red2(float2* p, float2 v) {
    asm volatile("red.global.add.v2.f32 [%0], {%1,%2};"
                 :: "l"(p), "f"(v.x), "f"(v.y) : "memory");
}
__device__ __forceinline__ void red4(float4* p, float4 v) {
    asm volatile("red.global.add.v4.f32 [%0], {%1,%2,%3,%4};"
                 :: "l"(p), "f"(v.x), "f"(v.y), "f"(v.z), "f"(v.w) : "memory");
}

// ---- degree count ----
__global__ void k_deg(const int* __restrict__ dst, int E) {
    int i = (blockIdx.x * blockDim.x + threadIdx.x) * 4;
    if (i + 3 < E) {
        int4 d = *(const int4*)(dst + i);
        atomicAdd(&g_deg[d.x], 1);
        atomicAdd(&g_deg[d.y], 1);
        atomicAdd(&g_deg[d.z], 1);
        atomicAdd(&g_deg[d.w], 1);
    } else {
        for (int j = i; j < E; j++) atomicAdd(&g_deg[dst[j]], 1);
    }
}

// ---- node pass 1: dinv, y = dinv * x, accA = y (self loop) ----
__global__ void k_node1(const float* __restrict__ x, int N) {
    int i = blockIdx.x * blockDim.x + threadIdx.x;
    if (i >= N) return;
    float dinv = rsqrtf((float)(g_deg[i] + 1));
    float2 xv = ((const float2*)x)[i];
    float2 y;
    y.x = dinv * xv.x;
    y.y = dinv * xv.y;
    g_dinv[i] = dinv;
    g_y[i]    = y;
    g_accA[i] = y;
}

// ---- scatter layer 1: accA[dst] += y[src]  (red.v2) ----
__global__ void k_scatter1(const int* __restrict__ src, const int* __restrict__ dst, int E) {
    int i = (blockIdx.x * blockDim.x + threadIdx.x) * 4;
    if (i + 3 < E) {
        int4 s = *(const int4*)(src + i);
        int4 d = *(const int4*)(dst + i);
        float2 a0 = g_y[s.x];
        float2 a1 = g_y[s.y];
        float2 a2 = g_y[s.z];
        float2 a3 = g_y[s.w];
        red2(&g_accA[d.x], a0);
        red2(&g_accA[d.y], a1);
        red2(&g_accA[d.z], a2);
        red2(&g_accA[d.w], a3);
    } else {
        for (int j = i; j < E; j++) red2(&g_accA[dst[j]], g_y[src[j]]);
    }
}

// ---- node pass 2: h1 = relu(dinv*(S@W1)+b1); featB = dinv*(h1@W2); accB = featB ----
__global__ void k_node2(int N) {
    int i = blockIdx.x * blockDim.x + threadIdx.x;
    if (i >= N) return;
    float dinv = g_dinv[i];
    float2 S = g_accA[i];
    // W1 [2,4] row-major at cW[0..7], b1 at cW[8..11]
    float h0 = fmaxf(dinv * (S.x * cW[0] + S.y * cW[4]) + cW[8],  0.0f);
    float h1 = fmaxf(dinv * (S.x * cW[1] + S.y * cW[5]) + cW[9],  0.0f);
    float h2 = fmaxf(dinv * (S.x * cW[2] + S.y * cW[6]) + cW[10], 0.0f);
    float h3 = fmaxf(dinv * (S.x * cW[3] + S.y * cW[7]) + cW[11], 0.0f);
    // W2 [4,3] row-major at cW[12..23]
    float4 g;
    g.x = dinv * (h0 * cW[12] + h1 * cW[15] + h2 * cW[18] + h3 * cW[21]);
    g.y = dinv * (h0 * cW[13] + h1 * cW[16] + h2 * cW[19] + h3 * cW[22]);
    g.z = dinv * (h0 * cW[14] + h1 * cW[17] + h2 * cW[20] + h3 * cW[23]);
    g.w = 0.0f;
    g_featB[i] = g;
    g_accB[i]  = g;
}

// ---- scatter layer 2: accB[dst] += featB[src]  (red.v4) ----
__global__ void k_scatter2(const int* __restrict__ src, const int* __restrict__ dst, int E) {
    int i = (blockIdx.x * blockDim.x + threadIdx.x) * 4;
    if (i + 3 < E) {
        int4 s = *(const int4*)(src + i);
        int4 d = *(const int4*)(dst + i);
        float4 a0 = g_featB[s.x];
        float4 a1 = g_featB[s.y];
        float4 a2 = g_featB[s.z];
        float4 a3 = g_featB[s.w];
        red4(&g_accB[d.x], a0);
        red4(&g_accB[d.y], a1);
        red4(&g_accB[d.z], a2);
        red4(&g_accB[d.w], a3);
    } else {
        for (int j = i; j < E; j++) red4(&g_accB[dst[j]], g_featB[src[j]]);
    }
}

// ---- node pass 3: sigmoid + MLP head ----
__global__ void k_node3(float* __restrict__ out, int N) {
    int i = blockIdx.x * blockDim.x + threadIdx.x;
    if (i >= N) return;
    float dinv = g_dinv[i];
    float4 a = g_accB[i];
    float q0 = 1.0f / (1.0f + expf(-(a.x * dinv + cW[24])));
    float q1 = 1.0f / (1.0f + expf(-(a.y * dinv + cW[25])));
    float q2 = 1.0f / (1.0f + expf(-(a.z * dinv + cW[26])));
    // h3 = relu(q @ W3[3,4] + b3), W3 at 27, b3 at 39
    float u0 = fmaxf(q0 * cW[27] + q1 * cW[31] + q2 * cW[35] + cW[39], 0.0f);
    float u1 = fmaxf(q0 * cW[28] + q1 * cW[32] + q2 * cW[36] + cW[40], 0.0f);
    float u2 = fmaxf(q0 * cW[29] + q1 * cW[33] + q2 * cW[37] + cW[41], 0.0f);
    float u3 = fmaxf(q0 * cW[30] + q1 * cW[34] + q2 * cW[38] + cW[42], 0.0f);
    // h4 = relu(u @ W4[4,3] + b4), W4 at 43, b4 at 55
    float v0 = fmaxf(u0 * cW[43] + u1 * cW[46] + u2 * cW[49] + u3 * cW[52] + cW[55], 0.0f);
    float v1 = fmaxf(u0 * cW[44] + u1 * cW[47] + u2 * cW[50] + u3 * cW[53] + cW[56], 0.0f);
    float v2 = fmaxf(u0 * cW[45] + u1 * cW[48] + u2 * cW[51] + u3 * cW[54] + cW[57], 0.0f);
    out[i] = v0 * cW[58] + v1 * cW[59] + v2 * cW[60] + cW[61];
}

extern "C" void kernel_launch(void* const* d_in, const int* in_sizes, int n_in,
                              void* d_out, int out_size) {
    const float* x    = (const float*)d_in[0];
    const int*   eidx = (const int*)d_in[1];
    int N = in_sizes[0] / 2;
    int E = in_sizes[1] / 2;
    const int* src = eidx;
    const int* dst = eidx + E;
    float* out = (float*)d_out;

    cudaMemcpyToSymbolAsync(cW, d_in[2],  8 * sizeof(float),  0 * sizeof(float), cudaMemcpyDeviceToDevice, 0); // W1
    cudaMemcpyToSymbolAsync(cW, d_in[3],  4 * sizeof(float),  8 * sizeof(float), cudaMemcpyDeviceToDevice, 0); // b1
    cudaMemcpyToSymbolAsync(cW, d_in[4], 12 * sizeof(float), 12 * sizeof(float), cudaMemcpyDeviceToDevice, 0); // W2
    cudaMemcpyToSymbolAsync(cW, d_in[5],  3 * sizeof(float), 24 * sizeof(float), cudaMemcpyDeviceToDevice, 0); // b2
    cudaMemcpyToSymbolAsync(cW, d_in[6], 12 * sizeof(float), 27 * sizeof(float), cudaMemcpyDeviceToDevice, 0); // W3
    cudaMemcpyToSymbolAsync(cW, d_in[7],  4 * sizeof(float), 39 * sizeof(float), cudaMemcpyDeviceToDevice, 0); // b3
    cudaMemcpyToSymbolAsync(cW, d_in[8], 12 * sizeof(float), 43 * sizeof(float), cudaMemcpyDeviceToDevice, 0); // W4
    cudaMemcpyToSymbolAsync(cW, d_in[9],  3 * sizeof(float), 55 * sizeof(float), cudaMemcpyDeviceToDevice, 0); // b4
    cudaMemcpyToSymbolAsync(cW, d_in[10], 3 * sizeof(float), 58 * sizeof(float), cudaMemcpyDeviceToDevice, 0); // W5
    cudaMemcpyToSymbolAsync(cW, d_in[11], 1 * sizeof(float), 61 * sizeof(float), cudaMemcpyDeviceToDevice, 0); // b5

    void* degPtr = nullptr;
    cudaGetSymbolAddress(&degPtr, g_deg);
    cudaMemsetAsync(degPtr, 0, N * sizeof(int), 0);

    int nodeBlocks = (N + NTHREADS - 1) / NTHREADS;
    int edgeBlocks = ((E + 3) / 4 + NTHREADS - 1) / NTHREADS;

    k_deg     <<<edgeBlocks, NTHREADS>>>(dst, E);
    k_node1   <<<nodeBlocks, NTHREADS>>>(x, N);
    k_scatter1<<<edgeBlocks, NTHREADS>>>(src, dst, E);
    k_node2   <<<nodeBlocks, NTHREADS>>>(N);
    k_scatter2<<<edgeBlocks, NTHREADS>>>(src, dst, E);
    k_node3   <<<nodeBlocks, NTHREADS>>>(out, N);
}